// round 4
// baseline (speedup 1.0000x reference)
#include <cuda_runtime.h>
#include <cuda_bf16.h>

// EISANI: sparse ternary net. B=512, F=128, NUM_BITS=16, E=2048, H=8192, C=10.
// Strategy:
//  1) extract_kernel: one memory-bound sweep over each dense f32 weight matrix,
//     emitting per-row nonzero column indices (positives front / negatives back
//     of a CAP-slot, padded to multiples of 4 with a zero-act sentinel index).
//  2) encode_kernel: thermometer bits, stored transposed as 32-batch bitwords.
//  3) layer_kernel: bit-sliced integer accumulation over 32 batches at once.
//     Two 6-plane counters (pos/neg) per lane; threshold z>=4 via bit-sliced
//     compare P + ~N >= 67; result word IS the next layer's activation word.
//  4) output_kernel: outAct = sum_i act_i @ outConn[i], deterministic reduce,
//     argmax -> preds.

#define HID 8192
#define ENC 2048
#define BATCH 512
#define NGRP 16          // 512 batches / 32
#define CAP 96           // max entries per row (mean 32, ~11 sigma headroom)
#define CLASSES 10

// ---------------- scratch (__device__ globals; no allocations) ----------------
__device__ unsigned short g_ent0[CAP * HID];
__device__ unsigned short g_ent1[CAP * HID];
__device__ unsigned short g_ent2[CAP * HID];
__device__ int g_cp0[HID], g_ns0[HID];
__device__ int g_cp1[HID], g_ns1[HID];
__device__ int g_cp2[HID], g_ns2[HID];
__device__ unsigned g_act0[NGRP * ENC];   // encoded input bits, transposed
__device__ unsigned g_act1[NGRP * HID];
__device__ unsigned g_act2[NGRP * HID];
__device__ unsigned g_act3[NGRP * HID];
__device__ float    g_sink[BATCH * CLASSES + BATCH];  // unused-output sink

// ---------------- 1) sparse extraction (HBM-bound sweep) ----------------
// One warp per row. Deterministic: fixed scan order, ballot/prefix appends.
__global__ __launch_bounds__(256) void extract_kernel(
    const float* __restrict__ W, int P,
    unsigned short* __restrict__ entT, int* __restrict__ cp4, int* __restrict__ ns4)
{
    int row  = (blockIdx.x * blockDim.x + threadIdx.x) >> 5;
    int lane = threadIdx.x & 31;
    unsigned lt = (1u << lane) - 1u;
    const float4* rp = reinterpret_cast<const float4*>(W + (size_t)row * P);
    int cp = 0, cn = 0;
    int nchunk = P >> 7;   // 128 columns per chunk (float4 per lane)
    for (int ch = 0; ch < nchunk; ch++) {
        float4 v = rp[ch * 32 + lane];
        int col = ch * 128 + lane * 4;
        float fs0 = v.x, fs1 = v.y, fs2 = v.z, fs3 = v.w;
        #pragma unroll
        for (int k = 0; k < 4; k++) {
            float f = (k == 0) ? fs0 : (k == 1) ? fs1 : (k == 2) ? fs2 : fs3;
            unsigned mp = __ballot_sync(0xFFFFFFFFu, f > 0.0f);
            unsigned mn = __ballot_sync(0xFFFFFFFFu, f < 0.0f);
            if (f > 0.0f) {
                int pos = cp + __popc(mp & lt);
                if (pos < CAP) entT[pos * HID + row] = (unsigned short)(col + k);
            } else if (f < 0.0f) {
                int pos = CAP - 1 - (cn + __popc(mn & lt));
                if (pos >= 0) entT[pos * HID + row] = (unsigned short)(col + k);
            }
            cp += __popc(mp);
            cn += __popc(mn);
        }
    }
    // clamp (6-bit counters => <=60 each; astronomically improbable to hit)
    cp = min(cp, 60); cn = min(cn, 60);
    int cpp = (cp + 3) & ~3;         // positives padded up
    int ns  = CAP - cn;              // negatives occupy [ns, CAP)
    int nsp = ns & ~3;               // padded down
    if (lane < cpp - cp) entT[(cp + lane) * HID + row] = (unsigned short)P;   // sentinel
    if (lane < ns - nsp) entT[(nsp + lane) * HID + row] = (unsigned short)P;
    if (lane == 0) { cp4[row] = cpp; ns4[row] = nsp; }
}

// ---------------- 2) thermometer encode, transposed bit layout ----------------
__global__ __launch_bounds__(256) void encode_kernel(
    const float* __restrict__ x, unsigned* __restrict__ act0T)
{
    int warp = (blockIdx.x * blockDim.x + threadIdx.x) >> 5;  // 0..2047
    int lane = threadIdx.x & 31;
    int g = warp >> 7;        // batch group 0..15
    int f = warp & 127;       // feature
    int b = g * 32 + lane;
    float xv = x[b * 128 + f] * 16.0f;
    unsigned myword = 0;
    #pragma unroll
    for (int j = 0; j < 16; j++) {
        unsigned m = __ballot_sync(0xFFFFFFFFu, xv > (float)j);
        if (lane == j) myword = m;
    }
    if (lane < 16) act0T[g * ENC + f * 16 + lane] = myword;
}

// ---------------- 3) bit-sliced layer ----------------
__device__ __forceinline__ void ripple6(unsigned (&a)[6], unsigned c) {
    #pragma unroll
    for (int i = 0; i < 6; i++) { unsigned t = a[i] & c; a[i] ^= c; c = t; }
}

template <int KDIM>
__global__ __launch_bounds__(256) void layer_kernel(
    const unsigned short* __restrict__ entT,
    const int* __restrict__ cp4, const int* __restrict__ ns4,
    const unsigned* __restrict__ actInT,   // [NGRP][KDIM]
    unsigned* __restrict__ actOutT)        // [NGRP][HID]
{
    __shared__ unsigned slice[KDIM + 1];
    int tid = threadIdx.x;
    int h = blockIdx.x * 256 + tid;
    int g = blockIdx.y;
    const unsigned* src = actInT + (size_t)g * KDIM;
    for (int i = tid; i < KDIM; i += 256) slice[i] = src[i];
    if (tid == 0) slice[KDIM] = 0u;   // sentinel (padding entries add 0)
    __syncthreads();

    int cp = cp4[h];
    int ns = ns4[h];
    unsigned p[6] = {0, 0, 0, 0, 0, 0};
    unsigned n[6] = {0, 0, 0, 0, 0, 0};

    const unsigned short* ep = entT + h;
    #pragma unroll 1
    for (int j = 0; j < cp; j += 4) {
        unsigned e0 = ep[(j + 0) * HID];
        unsigned e1 = ep[(j + 1) * HID];
        unsigned e2 = ep[(j + 2) * HID];
        unsigned e3 = ep[(j + 3) * HID];
        unsigned v0 = slice[e0], v1 = slice[e1], v2 = slice[e2], v3 = slice[e3];
        ripple6(p, v0); ripple6(p, v1); ripple6(p, v2); ripple6(p, v3);
    }
    #pragma unroll 1
    for (int j = ns; j < CAP; j += 4) {
        unsigned e0 = ep[(j + 0) * HID];
        unsigned e1 = ep[(j + 1) * HID];
        unsigned e2 = ep[(j + 2) * HID];
        unsigned e3 = ep[(j + 3) * HID];
        unsigned v0 = slice[e0], v1 = slice[e1], v2 = slice[e2], v3 = slice[e3];
        ripple6(n, v0); ripple6(n, v1); ripple6(n, v2); ripple6(n, v3);
    }

    // S = P + (63 - N) = P + ~N (6-bit). z = P - N >= 4  <=>  S >= 67.
    unsigned s[7];
    unsigned carry = 0;
    #pragma unroll
    for (int i = 0; i < 6; i++) {
        unsigned q = ~n[i];
        unsigned x1 = p[i] ^ q;
        s[i] = x1 ^ carry;
        carry = (p[i] & q) | (carry & x1);
    }
    s[6] = carry;
    // compare S >= 67 (1000011b), bit-sliced from MSB
    unsigned gt = 0, eq = 0xFFFFFFFFu;
    eq &= s[6];                              // C bit = 1
    #pragma unroll
    for (int i = 5; i >= 2; i--) {           // C bits = 0
        gt |= eq & s[i];
        eq &= ~s[i];
    }
    eq &= s[1];                              // C bit = 1
    eq &= s[0];                              // C bit = 1
    actOutT[(size_t)g * HID + h] = gt | eq;
}

// ---------------- 4) output: outAct + argmax ----------------
__global__ __launch_bounds__(256) void output_kernel(
    const unsigned* __restrict__ a1, const unsigned* __restrict__ a2,
    const unsigned* __restrict__ a3, const float* __restrict__ outConn,
    float* __restrict__ preds_out, float* __restrict__ outact_out)
{
    int b = blockIdx.x;
    int tid = threadIdx.x;
    int g = b >> 5, l = b & 31;
    float acc[CLASSES];
    #pragma unroll
    for (int c = 0; c < CLASSES; c++) acc[c] = 0.0f;

    const unsigned* r0 = a1 + (size_t)g * HID;
    const unsigned* r1 = a2 + (size_t)g * HID;
    const unsigned* r2 = a3 + (size_t)g * HID;

    for (int h = tid; h < HID; h += 256) {
        if ((r0[h] >> l) & 1) {
            const float* oc = outConn + (size_t)h * CLASSES;
            #pragma unroll
            for (int c = 0; c < CLASSES; c++) acc[c] += oc[c];
        }
        if ((r1[h] >> l) & 1) {
            const float* oc = outConn + (size_t)(HID + h) * CLASSES;
            #pragma unroll
            for (int c = 0; c < CLASSES; c++) acc[c] += oc[c];
        }
        if ((r2[h] >> l) & 1) {
            const float* oc = outConn + (size_t)(2 * HID + h) * CLASSES;
            #pragma unroll
            for (int c = 0; c < CLASSES; c++) acc[c] += oc[c];
        }
    }
    // deterministic reduce: warp shfl then cross-warp smem
    #pragma unroll
    for (int c = 0; c < CLASSES; c++) {
        #pragma unroll
        for (int off = 16; off > 0; off >>= 1)
            acc[c] += __shfl_down_sync(0xFFFFFFFFu, acc[c], off);
    }
    __shared__ float red[8][CLASSES];
    __shared__ float fin[CLASSES];
    int w = tid >> 5, ln = tid & 31;
    if (ln == 0) {
        #pragma unroll
        for (int c = 0; c < CLASSES; c++) red[w][c] = acc[c];
    }
    __syncthreads();
    if (tid < CLASSES) {
        float ss = 0.0f;
        #pragma unroll
        for (int w2 = 0; w2 < 8; w2++) ss += red[w2][tid];
        fin[tid] = ss;
        outact_out[b * CLASSES + tid] = ss;
    }
    __syncthreads();
    if (tid == 0) {
        int bi = 0;
        float bv = fin[0];
        #pragma unroll
        for (int c = 1; c < CLASSES; c++)
            if (fin[c] > bv) { bv = fin[c]; bi = c; }
        preds_out[b] = (float)bi;
    }
}

// ---------------- host ----------------
extern "C" void kernel_launch(void* const* d_in, const int* in_sizes, int n_in,
                              void* d_out, int out_size)
{
    // inputs: [0] trainOrTest (ignored), [1] x, [2] W0, [3] W1, [4] W2, [5] outConn
    const float* x       = (const float*)d_in[1];
    const float* W0      = (const float*)d_in[2];
    const float* W1      = (const float*)d_in[3];
    const float* W2      = (const float*)d_in[4];
    const float* outConn = (const float*)d_in[5];

    void *ent0, *ent1, *ent2, *cp0, *ns0, *cp1, *ns1, *cp2, *ns2;
    void *act0, *act1, *act2, *act3, *sink;
    cudaGetSymbolAddress(&ent0, g_ent0);  cudaGetSymbolAddress(&ent1, g_ent1);
    cudaGetSymbolAddress(&ent2, g_ent2);
    cudaGetSymbolAddress(&cp0, g_cp0);    cudaGetSymbolAddress(&ns0, g_ns0);
    cudaGetSymbolAddress(&cp1, g_cp1);    cudaGetSymbolAddress(&ns1, g_ns1);
    cudaGetSymbolAddress(&cp2, g_cp2);    cudaGetSymbolAddress(&ns2, g_ns2);
    cudaGetSymbolAddress(&act0, g_act0);  cudaGetSymbolAddress(&act1, g_act1);
    cudaGetSymbolAddress(&act2, g_act2);  cudaGetSymbolAddress(&act3, g_act3);
    cudaGetSymbolAddress(&sink, g_sink);

    // output layout (reference returns (preds, outAct)); assume float32
    float* preds_dst;
    float* outact_dst;
    if (out_size == BATCH * CLASSES + BATCH) {          // 5632: concat preds,outAct
        preds_dst  = (float*)d_out;
        outact_dst = (float*)d_out + BATCH;
    } else if (out_size == BATCH * CLASSES) {           // 5120: outAct only
        preds_dst  = (float*)sink;
        outact_dst = (float*)d_out;
    } else if (out_size == BATCH) {                     // 512: preds only
        preds_dst  = (float*)d_out;
        outact_dst = (float*)sink;
    } else {                                            // fallback: combined
        preds_dst  = (float*)d_out;
        outact_dst = (float*)d_out + BATCH;
    }

    // 1) sparse extraction of all three weight matrices (HBM-bound)
    extract_kernel<<<HID / 8, 256>>>(W0, ENC, (unsigned short*)ent0, (int*)cp0, (int*)ns0);
    extract_kernel<<<HID / 8, 256>>>(W1, HID, (unsigned short*)ent1, (int*)cp1, (int*)ns1);
    extract_kernel<<<HID / 8, 256>>>(W2, HID, (unsigned short*)ent2, (int*)cp2, (int*)ns2);

    // 2) thermometer encode
    encode_kernel<<<256, 256>>>(x, (unsigned*)act0);

    // 3) three bit-sliced layers
    dim3 lgrid(HID / 256, NGRP);
    layer_kernel<ENC><<<lgrid, 256>>>((unsigned short*)ent0, (int*)cp0, (int*)ns0,
                                      (unsigned*)act0, (unsigned*)act1);
    layer_kernel<HID><<<lgrid, 256>>>((unsigned short*)ent1, (int*)cp1, (int*)ns1,
                                      (unsigned*)act1, (unsigned*)act2);
    layer_kernel<HID><<<lgrid, 256>>>((unsigned short*)ent2, (int*)cp2, (int*)ns2,
                                      (unsigned*)act2, (unsigned*)act3);

    // 4) output accumulation + argmax
    output_kernel<<<BATCH, 256>>>((unsigned*)act1, (unsigned*)act2, (unsigned*)act3,
                                  outConn, preds_dst, outact_dst);
}

// round 5
// speedup vs baseline: 1.0548x; 1.0548x over previous
#include <cuda_runtime.h>
#include <cuda_bf16.h>

// EISANI sparse ternary net. B=512, F=128, NUM_BITS=16, E=2048, H=8192, C=10.
//  1) extract: grid-stride MLP=4 streaming sweep of dense f32 weights, per-thread
//     atomic append of nonzero column indices (pos front / neg back of CAP slot).
//     Order within a partition is irrelevant (sums are commutative) -> full
//     parallelism, no serial warp chain. pad_kernel rounds counts to mult of 4.
//  2) encode: thermometer bits, transposed 32-batch bitwords (smem-tiled).
//  3) layer: bit-sliced integer accumulation, 32 batches per word. Threshold
//     z>=4 as bit-sliced compare P + ~N >= 67.
//  4) output: smem-staged chunked accumulation (f32x2 packed FMA) into
//     per-chunk partials, then deterministic reduce + argmax.

#define HID 8192
#define ENC 2048
#define BATCH 512
#define NGRP 16
#define CAP 96
#define CLASSES 10
#define OCH 128                     // h-chunk for output stage
#define NCHUNK (3 * HID / OCH)      // 192

// ---------------- scratch ----------------
__device__ unsigned short g_ent0[CAP * HID];
__device__ unsigned short g_ent1[CAP * HID];
__device__ unsigned short g_ent2[CAP * HID];
__device__ int g_cnt[6 * HID];      // pc0,nc0,pc1,nc1,pc2,nc2
__device__ int g_cp0[HID], g_ns0[HID];
__device__ int g_cp1[HID], g_ns1[HID];
__device__ int g_cp2[HID], g_ns2[HID];
__device__ unsigned g_act0[NGRP * ENC];
__device__ unsigned g_act1[NGRP * HID];
__device__ unsigned g_act2[NGRP * HID];
__device__ unsigned g_act3[NGRP * HID];
__device__ float    g_part[NCHUNK * BATCH * CLASSES];
__device__ float    g_sink[BATCH * CLASSES + BATCH];

// ---------------- 1) extraction: streaming, atomic append ----------------
__global__ __launch_bounds__(256) void extract_kernel(
    const float4* __restrict__ W, int f4shf, int total_f4,
    unsigned short* __restrict__ entT, int* __restrict__ pc, int* __restrict__ nc)
{
    int t  = blockIdx.x * blockDim.x + threadIdx.x;
    int NT = gridDim.x * blockDim.x;
    int f4mask = (1 << f4shf) - 1;

    for (int base = 0; base < total_f4; base += NT * 4) {
        float4 v[4];
        int idx[4];
        bool ok[4];
        #pragma unroll
        for (int j = 0; j < 4; j++) {
            idx[j] = base + t + j * NT;
            ok[j] = idx[j] < total_f4;
            if (ok[j]) v[j] = __ldcs(W + idx[j]);
            else       v[j] = make_float4(0.f, 0.f, 0.f, 0.f);
        }
        #pragma unroll
        for (int j = 0; j < 4; j++) {
            float f0 = v[j].x, f1 = v[j].y, f2 = v[j].z, f3 = v[j].w;
            int cntp = (f0 > 0.f) + (f1 > 0.f) + (f2 > 0.f) + (f3 > 0.f);
            int cntn = (f0 < 0.f) + (f1 < 0.f) + (f2 < 0.f) + (f3 < 0.f);
            if ((cntp | cntn) == 0) continue;
            int row  = idx[j] >> f4shf;
            int col4 = (idx[j] & f4mask) << 2;
            if (cntp) {
                int bp = atomicAdd(&pc[row], cntp);
                float ff[4] = {f0, f1, f2, f3};
                #pragma unroll
                for (int k = 0; k < 4; k++) {
                    if (ff[k] > 0.f) {
                        if (bp < CAP) entT[bp * HID + row] = (unsigned short)(col4 + k);
                        bp++;
                    }
                }
            }
            if (cntn) {
                int bn = atomicAdd(&nc[row], cntn);
                float ff[4] = {f0, f1, f2, f3};
                #pragma unroll
                for (int k = 0; k < 4; k++) {
                    if (ff[k] < 0.f) {
                        int sl = CAP - 1 - bn;
                        if (sl >= 0) entT[sl * HID + row] = (unsigned short)(col4 + k);
                        bn++;
                    }
                }
            }
        }
    }
}

__global__ void pad_kernel(const int* __restrict__ pc, const int* __restrict__ nc,
                           int P, unsigned short* __restrict__ entT,
                           int* __restrict__ cp4, int* __restrict__ ns4)
{
    int row = blockIdx.x * blockDim.x + threadIdx.x;
    if (row >= HID) return;
    int cp = min(pc[row], 60);
    int cn = min(nc[row], 60);
    int cpp = (cp + 3) & ~3;
    for (int j = cp; j < cpp; j++) entT[j * HID + row] = (unsigned short)P;
    int ns  = CAP - cn;
    int nsp = ns & ~3;
    for (int j = nsp; j < ns; j++) entT[j * HID + row] = (unsigned short)P;
    cp4[row] = cpp;
    ns4[row] = nsp;
}

// ---------------- 2) thermometer encode (smem-tiled, coalesced) -------------
__global__ __launch_bounds__(256) void encode_kernel(
    const float* __restrict__ x, unsigned* __restrict__ act0T)
{
    __shared__ float xs[32 * 129];
    int g = blockIdx.x;            // 16 batch groups
    int tid = threadIdx.x;
    const float* xg = x + (size_t)g * 32 * 128;
    for (int i = tid; i < 4096; i += 256)
        xs[(i >> 7) * 129 + (i & 127)] = xg[i];
    __syncthreads();
    int w = tid >> 5, lane = tid & 31;
    for (int f = w; f < 128; f += 8) {
        float xv = xs[lane * 129 + f] * 16.0f;
        unsigned myword = 0;
        #pragma unroll
        for (int j = 0; j < 16; j++) {
            unsigned m = __ballot_sync(0xFFFFFFFFu, xv > (float)j);
            if (lane == j) myword = m;
        }
        if (lane < 16) act0T[g * ENC + f * 16 + lane] = myword;
    }
}

// ---------------- 3) bit-sliced layer ----------------
__device__ __forceinline__ void ripple6(unsigned (&a)[6], unsigned c) {
    #pragma unroll
    for (int i = 0; i < 6; i++) { unsigned t = a[i] & c; a[i] ^= c; c = t; }
}

template <int KDIM>
__global__ __launch_bounds__(256) void layer_kernel(
    const unsigned short* __restrict__ entT,
    const int* __restrict__ cp4, const int* __restrict__ ns4,
    const unsigned* __restrict__ actInT,
    unsigned* __restrict__ actOutT)
{
    __shared__ unsigned slice[KDIM + 1];
    int tid = threadIdx.x;
    int h = blockIdx.x * 256 + tid;
    int g = blockIdx.y;
    const unsigned* src = actInT + (size_t)g * KDIM;
    for (int i = tid; i < KDIM; i += 256) slice[i] = src[i];
    if (tid == 0) slice[KDIM] = 0u;
    __syncthreads();

    int cp = cp4[h];
    int ns = ns4[h];
    unsigned p[6] = {0, 0, 0, 0, 0, 0};
    unsigned n[6] = {0, 0, 0, 0, 0, 0};
    const unsigned short* ep = entT + h;

    #pragma unroll 1
    for (int j = 0; j < cp; j += 4) {
        unsigned e0 = ep[(j + 0) * HID], e1 = ep[(j + 1) * HID];
        unsigned e2 = ep[(j + 2) * HID], e3 = ep[(j + 3) * HID];
        unsigned v0 = slice[e0], v1 = slice[e1], v2 = slice[e2], v3 = slice[e3];
        ripple6(p, v0); ripple6(p, v1); ripple6(p, v2); ripple6(p, v3);
    }
    #pragma unroll 1
    for (int j = ns; j < CAP; j += 4) {
        unsigned e0 = ep[(j + 0) * HID], e1 = ep[(j + 1) * HID];
        unsigned e2 = ep[(j + 2) * HID], e3 = ep[(j + 3) * HID];
        unsigned v0 = slice[e0], v1 = slice[e1], v2 = slice[e2], v3 = slice[e3];
        ripple6(n, v0); ripple6(n, v1); ripple6(n, v2); ripple6(n, v3);
    }

    // S = P + ~N (6-bit); z = P - N >= 4 <=> S >= 67 (1000011b)
    unsigned s[7], carry = 0;
    #pragma unroll
    for (int i = 0; i < 6; i++) {
        unsigned q = ~n[i];
        unsigned x1 = p[i] ^ q;
        s[i] = x1 ^ carry;
        carry = (p[i] & q) | (carry & x1);
    }
    s[6] = carry;
    unsigned gt = 0, eq = 0xFFFFFFFFu;
    eq &= s[6];
    #pragma unroll
    for (int i = 5; i >= 2; i--) { gt |= eq & s[i]; eq &= ~s[i]; }
    eq &= s[1];
    eq &= s[0];
    actOutT[(size_t)g * HID + h] = gt | eq;
}

// ---------------- 4a) output partials: smem-staged, f32x2 FMA ---------------
__global__ __launch_bounds__(256) void outpart_kernel(
    const unsigned* __restrict__ a1, const unsigned* __restrict__ a2,
    const unsigned* __restrict__ a3, const float* __restrict__ outConn,
    float* __restrict__ part)
{
    __shared__ float    ocs[OCH * CLASSES];   // 5 KB
    __shared__ unsigned ws[OCH * 8];          // 4 KB
    int chunk = blockIdx.x;                   // 0..191
    int half  = blockIdx.y;                   // 0..1
    int layer = chunk >> 6;
    int hbase = (chunk & 63) * OCH;
    const unsigned* act = (layer == 0) ? a1 : (layer == 1) ? a2 : a3;
    const float* oc = outConn + ((size_t)layer * HID + hbase) * CLASSES;
    int tid = threadIdx.x;
    for (int i = tid; i < OCH * CLASSES; i += 256) ocs[i] = oc[i];
    for (int i = tid; i < OCH * 8; i += 256) {
        int hh = i >> 3, gl = i & 7;
        ws[i] = act[(size_t)(half * 8 + gl) * HID + hbase + hh];
    }
    __syncthreads();

    int gl = tid >> 5, lane = tid & 31;
    int b = half * 256 + tid;
    unsigned long long acc[5] = {0ull, 0ull, 0ull, 0ull, 0ull};

    #pragma unroll 4
    for (int hh = 0; hh < OCH; hh++) {
        unsigned w = ws[hh * 8 + gl];
        unsigned bfbits = ((w >> lane) & 1u) ? 0x3f800000u : 0u;
        unsigned long long bfp = (unsigned long long)bfbits |
                                 ((unsigned long long)bfbits << 32);
        const unsigned long long* ocp =
            reinterpret_cast<const unsigned long long*>(&ocs[hh * CLASSES]);
        #pragma unroll
        for (int i = 0; i < 5; i++) {
            unsigned long long o = ocp[i];
            asm("fma.rn.f32x2 %0, %1, %2, %0;" : "+l"(acc[i]) : "l"(bfp), "l"(o));
        }
    }
    float* dst = part + ((size_t)chunk * BATCH + b) * CLASSES;
    #pragma unroll
    for (int i = 0; i < 5; i++) {
        unsigned lo = (unsigned)(acc[i] & 0xFFFFFFFFull);
        unsigned hi = (unsigned)(acc[i] >> 32);
        dst[2 * i + 0] = __uint_as_float(lo);
        dst[2 * i + 1] = __uint_as_float(hi);
    }
}

// ---------------- 4b) deterministic reduce + argmax ----------------
__global__ void outfinal_kernel(const float* __restrict__ part,
                                float* __restrict__ preds_out,
                                float* __restrict__ outact_out)
{
    int b = blockIdx.x;
    int tid = threadIdx.x;   // 32 threads
    __shared__ float fin[CLASSES];
    if (tid < CLASSES) {
        float s0 = 0.f, s1 = 0.f, s2 = 0.f, s3 = 0.f;
        #pragma unroll 1
        for (int ch = 0; ch < NCHUNK; ch += 4) {
            s0 += part[((size_t)(ch + 0) * BATCH + b) * CLASSES + tid];
            s1 += part[((size_t)(ch + 1) * BATCH + b) * CLASSES + tid];
            s2 += part[((size_t)(ch + 2) * BATCH + b) * CLASSES + tid];
            s3 += part[((size_t)(ch + 3) * BATCH + b) * CLASSES + tid];
        }
        float s = (s0 + s1) + (s2 + s3);
        fin[tid] = s;
        outact_out[b * CLASSES + tid] = s;
    }
    __syncthreads();
    if (tid == 0) {
        int bi = 0;
        float bv = fin[0];
        #pragma unroll
        for (int c = 1; c < CLASSES; c++)
            if (fin[c] > bv) { bv = fin[c]; bi = c; }
        preds_out[b] = (float)bi;
    }
}

// ---------------- host ----------------
extern "C" void kernel_launch(void* const* d_in, const int* in_sizes, int n_in,
                              void* d_out, int out_size)
{
    const float* x       = (const float*)d_in[1];
    const float* W0      = (const float*)d_in[2];
    const float* W1      = (const float*)d_in[3];
    const float* W2      = (const float*)d_in[4];
    const float* outConn = (const float*)d_in[5];

    void *ent0, *ent1, *ent2, *cnt;
    void *cp0, *ns0, *cp1, *ns1, *cp2, *ns2;
    void *act0, *act1, *act2, *act3, *part, *sink;
    cudaGetSymbolAddress(&ent0, g_ent0);  cudaGetSymbolAddress(&ent1, g_ent1);
    cudaGetSymbolAddress(&ent2, g_ent2);  cudaGetSymbolAddress(&cnt,  g_cnt);
    cudaGetSymbolAddress(&cp0, g_cp0);    cudaGetSymbolAddress(&ns0, g_ns0);
    cudaGetSymbolAddress(&cp1, g_cp1);    cudaGetSymbolAddress(&ns1, g_ns1);
    cudaGetSymbolAddress(&cp2, g_cp2);    cudaGetSymbolAddress(&ns2, g_ns2);
    cudaGetSymbolAddress(&act0, g_act0);  cudaGetSymbolAddress(&act1, g_act1);
    cudaGetSymbolAddress(&act2, g_act2);  cudaGetSymbolAddress(&act3, g_act3);
    cudaGetSymbolAddress(&part, g_part);  cudaGetSymbolAddress(&sink, g_sink);

    int* pc0 = (int*)cnt;          int* nc0 = pc0 + HID;
    int* pc1 = nc0 + HID;          int* nc1 = pc1 + HID;
    int* pc2 = nc1 + HID;          int* nc2 = pc2 + HID;

    float* preds_dst;
    float* outact_dst;
    if (out_size == BATCH * CLASSES + BATCH) {
        preds_dst  = (float*)d_out;
        outact_dst = (float*)d_out + BATCH;
    } else if (out_size == BATCH * CLASSES) {
        preds_dst  = (float*)sink;
        outact_dst = (float*)d_out;
    } else if (out_size == BATCH) {
        preds_dst  = (float*)d_out;
        outact_dst = (float*)sink;
    } else {
        preds_dst  = (float*)d_out;
        outact_dst = (float*)d_out + BATCH;
    }

    cudaMemsetAsync(cnt, 0, 6 * HID * sizeof(int), 0);

    const int XGRID = 1184;  // 8 blocks/SM x 148
    extract_kernel<<<XGRID, 256>>>((const float4*)W0, 9,  HID * (ENC / 4),
                                   (unsigned short*)ent0, pc0, nc0);
    extract_kernel<<<XGRID, 256>>>((const float4*)W1, 11, HID * (HID / 4),
                                   (unsigned short*)ent1, pc1, nc1);
    extract_kernel<<<XGRID, 256>>>((const float4*)W2, 11, HID * (HID / 4),
                                   (unsigned short*)ent2, pc2, nc2);

    pad_kernel<<<HID / 256, 256>>>(pc0, nc0, ENC, (unsigned short*)ent0, (int*)cp0, (int*)ns0);
    pad_kernel<<<HID / 256, 256>>>(pc1, nc1, HID, (unsigned short*)ent1, (int*)cp1, (int*)ns1);
    pad_kernel<<<HID / 256, 256>>>(pc2, nc2, HID, (unsigned short*)ent2, (int*)cp2, (int*)ns2);

    encode_kernel<<<NGRP, 256>>>(x, (unsigned*)act0);

    dim3 lgrid(HID / 256, NGRP);
    layer_kernel<ENC><<<lgrid, 256>>>((unsigned short*)ent0, (int*)cp0, (int*)ns0,
                                      (unsigned*)act0, (unsigned*)act1);
    layer_kernel<HID><<<lgrid, 256>>>((unsigned short*)ent1, (int*)cp1, (int*)ns1,
                                      (unsigned*)act1, (unsigned*)act2);
    layer_kernel<HID><<<lgrid, 256>>>((unsigned short*)ent2, (int*)cp2, (int*)ns2,
                                      (unsigned*)act2, (unsigned*)act3);

    dim3 ogrid(NCHUNK, 2);
    outpart_kernel<<<ogrid, 256>>>((unsigned*)act1, (unsigned*)act2, (unsigned*)act3,
                                   outConn, (float*)part);
    outfinal_kernel<<<BATCH, 32>>>((float*)part, preds_dst, outact_dst);
}

// round 6
// speedup vs baseline: 1.2818x; 1.2152x over previous
#include <cuda_runtime.h>
#include <cuda_bf16.h>

// EISANI sparse ternary net. B=512, F=128, NUM_BITS=16, E=2048, H=8192, C=10.
// R5: graph restructure. Side-stream (fork/join in capture) runs
// encode -> extract W0 -> pad0 -> layer0 under the shadow of the two big
// W1/W2 extraction sweeps on the main stream. memset removed (counts zeroed
// at tail of outfinal; identical state every call). pads fused.

#define HID 8192
#define ENC 2048
#define BATCH 512
#define NGRP 16
#define CAP 96
#define CLASSES 10
#define OCH 128
#define NCHUNK (3 * HID / OCH)      // 192

// ---------------- scratch ----------------
__device__ unsigned short g_ent0[CAP * HID];
__device__ unsigned short g_ent1[CAP * HID];
__device__ unsigned short g_ent2[CAP * HID];
__device__ int g_cnt[6 * HID];      // pc0,nc0,pc1,nc1,pc2,nc2 (zeroed by outfinal)
__device__ int g_cp0[HID], g_ns0[HID];
__device__ int g_cp1[HID], g_ns1[HID];
__device__ int g_cp2[HID], g_ns2[HID];
__device__ unsigned g_act0[NGRP * ENC];
__device__ unsigned g_act1[NGRP * HID];
__device__ unsigned g_act2[NGRP * HID];
__device__ unsigned g_act3[NGRP * HID];
__device__ float    g_part[NCHUNK * BATCH * CLASSES];
__device__ float    g_sink[BATCH * CLASSES + BATCH];

// ---------------- 1) extraction: streaming, atomic append ----------------
__global__ __launch_bounds__(256) void extract_kernel(
    const float4* __restrict__ W, int f4shf, int total_f4,
    unsigned short* __restrict__ entT, int* __restrict__ pc, int* __restrict__ nc)
{
    int t  = blockIdx.x * blockDim.x + threadIdx.x;
    int NT = gridDim.x * blockDim.x;
    int f4mask = (1 << f4shf) - 1;

    for (int base = 0; base < total_f4; base += NT * 4) {
        float4 v[4];
        int idx[4];
        #pragma unroll
        for (int j = 0; j < 4; j++) {
            idx[j] = base + t + j * NT;
            if (idx[j] < total_f4) v[j] = __ldcs(W + idx[j]);
            else                   v[j] = make_float4(0.f, 0.f, 0.f, 0.f);
        }
        #pragma unroll
        for (int j = 0; j < 4; j++) {
            float f0 = v[j].x, f1 = v[j].y, f2 = v[j].z, f3 = v[j].w;
            int cntp = (f0 > 0.f) + (f1 > 0.f) + (f2 > 0.f) + (f3 > 0.f);
            int cntn = (f0 < 0.f) + (f1 < 0.f) + (f2 < 0.f) + (f3 < 0.f);
            if ((cntp | cntn) == 0) continue;
            int row  = idx[j] >> f4shf;
            int col4 = (idx[j] & f4mask) << 2;
            if (cntp) {
                int bp = atomicAdd(&pc[row], cntp);
                float ff[4] = {f0, f1, f2, f3};
                #pragma unroll
                for (int k = 0; k < 4; k++) {
                    if (ff[k] > 0.f) {
                        if (bp < CAP) entT[bp * HID + row] = (unsigned short)(col4 + k);
                        bp++;
                    }
                }
            }
            if (cntn) {
                int bn = atomicAdd(&nc[row], cntn);
                float ff[4] = {f0, f1, f2, f3};
                #pragma unroll
                for (int k = 0; k < 4; k++) {
                    if (ff[k] < 0.f) {
                        int sl = CAP - 1 - bn;
                        if (sl >= 0) entT[sl * HID + row] = (unsigned short)(col4 + k);
                        bn++;
                    }
                }
            }
        }
    }
}

// ---------------- pad: round counts to mult of 4 with sentinels -------------
__device__ __forceinline__ void pad_row(int row, const int* pc, const int* nc,
                                        int P, unsigned short* entT,
                                        int* cp4, int* ns4)
{
    int cp = min(pc[row], 60);
    int cn = min(nc[row], 60);
    int cpp = (cp + 3) & ~3;
    for (int j = cp; j < cpp; j++) entT[j * HID + row] = (unsigned short)P;
    int ns  = CAP - cn;
    int nsp = ns & ~3;
    for (int j = nsp; j < ns; j++) entT[j * HID + row] = (unsigned short)P;
    cp4[row] = cpp;
    ns4[row] = nsp;
}

__global__ void pad_kernel(const int* __restrict__ pc, const int* __restrict__ nc,
                           int P, unsigned short* __restrict__ entT,
                           int* __restrict__ cp4, int* __restrict__ ns4)
{
    int row = blockIdx.x * blockDim.x + threadIdx.x;
    if (row < HID) pad_row(row, pc, nc, P, entT, cp4, ns4);
}

__global__ void pad2_kernel(
    const int* __restrict__ pcA, const int* __restrict__ ncA,
    unsigned short* __restrict__ eA, int* __restrict__ cpA, int* __restrict__ nsA,
    const int* __restrict__ pcB, const int* __restrict__ ncB,
    unsigned short* __restrict__ eB, int* __restrict__ cpB, int* __restrict__ nsB)
{
    int row = blockIdx.x * blockDim.x + threadIdx.x;
    if (row >= HID) return;
    if (blockIdx.y == 0) pad_row(row, pcA, ncA, HID, eA, cpA, nsA);
    else                 pad_row(row, pcB, ncB, HID, eB, cpB, nsB);
}

// ---------------- 2) thermometer encode ----------------
__global__ __launch_bounds__(256) void encode_kernel(
    const float* __restrict__ x, unsigned* __restrict__ act0T)
{
    __shared__ float xs[32 * 129];
    int g = blockIdx.x;
    int tid = threadIdx.x;
    const float* xg = x + (size_t)g * 32 * 128;
    for (int i = tid; i < 4096; i += 256)
        xs[(i >> 7) * 129 + (i & 127)] = xg[i];
    __syncthreads();
    int w = tid >> 5, lane = tid & 31;
    for (int f = w; f < 128; f += 8) {
        float xv = xs[lane * 129 + f] * 16.0f;
        unsigned myword = 0;
        #pragma unroll
        for (int j = 0; j < 16; j++) {
            unsigned m = __ballot_sync(0xFFFFFFFFu, xv > (float)j);
            if (lane == j) myword = m;
        }
        if (lane < 16) act0T[g * ENC + f * 16 + lane] = myword;
    }
}

// ---------------- 3) bit-sliced layer ----------------
__device__ __forceinline__ void ripple6(unsigned (&a)[6], unsigned c) {
    #pragma unroll
    for (int i = 0; i < 6; i++) { unsigned t = a[i] & c; a[i] ^= c; c = t; }
}

template <int KDIM>
__global__ __launch_bounds__(256) void layer_kernel(
    const unsigned short* __restrict__ entT,
    const int* __restrict__ cp4, const int* __restrict__ ns4,
    const unsigned* __restrict__ actInT,
    unsigned* __restrict__ actOutT)
{
    __shared__ unsigned slice[KDIM + 1];
    int tid = threadIdx.x;
    int h = blockIdx.x * 256 + tid;
    int g = blockIdx.y;
    const unsigned* src = actInT + (size_t)g * KDIM;
    for (int i = tid; i < KDIM; i += 256) slice[i] = src[i];
    if (tid == 0) slice[KDIM] = 0u;
    __syncthreads();

    int cp = cp4[h];
    int ns = ns4[h];
    unsigned p[6] = {0, 0, 0, 0, 0, 0};
    unsigned n[6] = {0, 0, 0, 0, 0, 0};
    const unsigned short* ep = entT + h;

    #pragma unroll 1
    for (int j = 0; j < cp; j += 4) {
        unsigned e0 = ep[(j + 0) * HID], e1 = ep[(j + 1) * HID];
        unsigned e2 = ep[(j + 2) * HID], e3 = ep[(j + 3) * HID];
        unsigned v0 = slice[e0], v1 = slice[e1], v2 = slice[e2], v3 = slice[e3];
        ripple6(p, v0); ripple6(p, v1); ripple6(p, v2); ripple6(p, v3);
    }
    #pragma unroll 1
    for (int j = ns; j < CAP; j += 4) {
        unsigned e0 = ep[(j + 0) * HID], e1 = ep[(j + 1) * HID];
        unsigned e2 = ep[(j + 2) * HID], e3 = ep[(j + 3) * HID];
        unsigned v0 = slice[e0], v1 = slice[e1], v2 = slice[e2], v3 = slice[e3];
        ripple6(n, v0); ripple6(n, v1); ripple6(n, v2); ripple6(n, v3);
    }

    // S = P + ~N (6-bit); z = P - N >= 4 <=> S >= 67 (1000011b)
    unsigned s[7], carry = 0;
    #pragma unroll
    for (int i = 0; i < 6; i++) {
        unsigned q = ~n[i];
        unsigned x1 = p[i] ^ q;
        s[i] = x1 ^ carry;
        carry = (p[i] & q) | (carry & x1);
    }
    s[6] = carry;
    unsigned gt = 0, eq = 0xFFFFFFFFu;
    eq &= s[6];
    #pragma unroll
    for (int i = 5; i >= 2; i--) { gt |= eq & s[i]; eq &= ~s[i]; }
    eq &= s[1];
    eq &= s[0];
    actOutT[(size_t)g * HID + h] = gt | eq;
}

// ---------------- 4a) output partials ----------------
__global__ __launch_bounds__(256) void outpart_kernel(
    const unsigned* __restrict__ a1, const unsigned* __restrict__ a2,
    const unsigned* __restrict__ a3, const float* __restrict__ outConn,
    float* __restrict__ part)
{
    __shared__ float    ocs[OCH * CLASSES];
    __shared__ unsigned ws[OCH * 8];
    int chunk = blockIdx.x;
    int half  = blockIdx.y;
    int layer = chunk >> 6;
    int hbase = (chunk & 63) * OCH;
    const unsigned* act = (layer == 0) ? a1 : (layer == 1) ? a2 : a3;
    const float* oc = outConn + ((size_t)layer * HID + hbase) * CLASSES;
    int tid = threadIdx.x;
    for (int i = tid; i < OCH * CLASSES; i += 256) ocs[i] = oc[i];
    for (int i = tid; i < OCH * 8; i += 256) {
        int hh = i >> 3, gl = i & 7;
        ws[i] = act[(size_t)(half * 8 + gl) * HID + hbase + hh];
    }
    __syncthreads();

    int gl = tid >> 5, lane = tid & 31;
    int b = half * 256 + tid;
    unsigned long long acc[5] = {0ull, 0ull, 0ull, 0ull, 0ull};

    #pragma unroll 4
    for (int hh = 0; hh < OCH; hh++) {
        unsigned w = ws[hh * 8 + gl];
        unsigned bfbits = ((w >> lane) & 1u) ? 0x3f800000u : 0u;
        unsigned long long bfp = (unsigned long long)bfbits |
                                 ((unsigned long long)bfbits << 32);
        const unsigned long long* ocp =
            reinterpret_cast<const unsigned long long*>(&ocs[hh * CLASSES]);
        #pragma unroll
        for (int i = 0; i < 5; i++) {
            unsigned long long o = ocp[i];
            asm("fma.rn.f32x2 %0, %1, %2, %0;" : "+l"(acc[i]) : "l"(bfp), "l"(o));
        }
    }
    float* dst = part + ((size_t)chunk * BATCH + b) * CLASSES;
    #pragma unroll
    for (int i = 0; i < 5; i++) {
        unsigned lo = (unsigned)(acc[i] & 0xFFFFFFFFull);
        unsigned hi = (unsigned)(acc[i] >> 32);
        dst[2 * i + 0] = __uint_as_float(lo);
        dst[2 * i + 1] = __uint_as_float(hi);
    }
}

// ---------------- 4b) reduce + argmax + zero counts for next call -----------
__global__ __launch_bounds__(320) void outfinal_kernel(
    const float* __restrict__ part, float* __restrict__ preds_out,
    float* __restrict__ outact_out, int* __restrict__ cnt)
{
    int b = blockIdx.x;
    int t = threadIdx.x;            // 320 = 10 warps (one per class)
    if (t < 96) cnt[b * 96 + t] = 0;   // 512*96 = 6*HID
    int w = t >> 5, l = t & 31;
    __shared__ float fin[CLASSES];
    float s = 0.f;
    #pragma unroll
    for (int i = 0; i < 6; i++) {
        int ch = l + i * 32;        // 6*32 = 192 = NCHUNK
        s += part[((size_t)ch * BATCH + b) * CLASSES + w];
    }
    #pragma unroll
    for (int off = 16; off > 0; off >>= 1)
        s += __shfl_down_sync(0xFFFFFFFFu, s, off);
    if (l == 0) {
        fin[w] = s;
        outact_out[b * CLASSES + w] = s;
    }
    __syncthreads();
    if (t == 0) {
        int bi = 0;
        float bv = fin[0];
        #pragma unroll
        for (int c = 1; c < CLASSES; c++)
            if (fin[c] > bv) { bv = fin[c]; bi = c; }
        preds_out[b] = (float)bi;
    }
}

// ---------------- host ----------------
static cudaStream_t s_side = nullptr;
static cudaEvent_t  s_evFork = nullptr, s_evJoin = nullptr;

extern "C" void kernel_launch(void* const* d_in, const int* in_sizes, int n_in,
                              void* d_out, int out_size)
{
    const float* x       = (const float*)d_in[1];
    const float* W0      = (const float*)d_in[2];
    const float* W1      = (const float*)d_in[3];
    const float* W2      = (const float*)d_in[4];
    const float* outConn = (const float*)d_in[5];

    if (!s_side) {
        cudaStreamCreateWithFlags(&s_side, cudaStreamNonBlocking);
        cudaEventCreateWithFlags(&s_evFork, cudaEventDisableTiming);
        cudaEventCreateWithFlags(&s_evJoin, cudaEventDisableTiming);
    }

    void *ent0, *ent1, *ent2, *cnt;
    void *cp0, *ns0, *cp1, *ns1, *cp2, *ns2;
    void *act0, *act1, *act2, *act3, *part, *sink;
    cudaGetSymbolAddress(&ent0, g_ent0);  cudaGetSymbolAddress(&ent1, g_ent1);
    cudaGetSymbolAddress(&ent2, g_ent2);  cudaGetSymbolAddress(&cnt,  g_cnt);
    cudaGetSymbolAddress(&cp0, g_cp0);    cudaGetSymbolAddress(&ns0, g_ns0);
    cudaGetSymbolAddress(&cp1, g_cp1);    cudaGetSymbolAddress(&ns1, g_ns1);
    cudaGetSymbolAddress(&cp2, g_cp2);    cudaGetSymbolAddress(&ns2, g_ns2);
    cudaGetSymbolAddress(&act0, g_act0);  cudaGetSymbolAddress(&act1, g_act1);
    cudaGetSymbolAddress(&act2, g_act2);  cudaGetSymbolAddress(&act3, g_act3);
    cudaGetSymbolAddress(&part, g_part);  cudaGetSymbolAddress(&sink, g_sink);

    int* pc0 = (int*)cnt;          int* nc0 = pc0 + HID;
    int* pc1 = nc0 + HID;          int* nc1 = pc1 + HID;
    int* pc2 = nc1 + HID;          int* nc2 = pc2 + HID;

    float* preds_dst;
    float* outact_dst;
    if (out_size == BATCH * CLASSES + BATCH) {
        preds_dst  = (float*)d_out;
        outact_dst = (float*)d_out + BATCH;
    } else if (out_size == BATCH * CLASSES) {
        preds_dst  = (float*)sink;
        outact_dst = (float*)d_out;
    } else if (out_size == BATCH) {
        preds_dst  = (float*)d_out;
        outact_dst = (float*)sink;
    } else {
        preds_dst  = (float*)d_out;
        outact_dst = (float*)d_out + BATCH;
    }

    const int XGRID = 1184;
    dim3 lgrid(HID / 256, NGRP);

    // ---- fork side chain (runs under W1/W2 extraction shadow) ----
    cudaEventRecord(s_evFork, 0);
    cudaStreamWaitEvent(s_side, s_evFork, 0);

    encode_kernel<<<NGRP, 256, 0, s_side>>>(x, (unsigned*)act0);
    extract_kernel<<<XGRID, 256, 0, s_side>>>((const float4*)W0, 9, HID * (ENC / 4),
                                              (unsigned short*)ent0, pc0, nc0);
    pad_kernel<<<HID / 256, 256, 0, s_side>>>(pc0, nc0, ENC, (unsigned short*)ent0,
                                              (int*)cp0, (int*)ns0);
    layer_kernel<ENC><<<lgrid, 256, 0, s_side>>>((unsigned short*)ent0, (int*)cp0,
                                                 (int*)ns0, (unsigned*)act0,
                                                 (unsigned*)act1);
    cudaEventRecord(s_evJoin, s_side);

    // ---- main chain: the two big HBM sweeps ----
    extract_kernel<<<XGRID, 256>>>((const float4*)W1, 11, HID * (HID / 4),
                                   (unsigned short*)ent1, pc1, nc1);
    extract_kernel<<<XGRID, 256>>>((const float4*)W2, 11, HID * (HID / 4),
                                   (unsigned short*)ent2, pc2, nc2);
    dim3 pgrid(HID / 256, 2);
    pad2_kernel<<<pgrid, 256>>>(pc1, nc1, (unsigned short*)ent1, (int*)cp1, (int*)ns1,
                                pc2, nc2, (unsigned short*)ent2, (int*)cp2, (int*)ns2);

    cudaStreamWaitEvent(0, s_evJoin, 0);

    layer_kernel<HID><<<lgrid, 256>>>((unsigned short*)ent1, (int*)cp1, (int*)ns1,
                                      (unsigned*)act1, (unsigned*)act2);
    layer_kernel<HID><<<lgrid, 256>>>((unsigned short*)ent2, (int*)cp2, (int*)ns2,
                                      (unsigned*)act2, (unsigned*)act3);

    dim3 ogrid(NCHUNK, 2);
    outpart_kernel<<<ogrid, 256>>>((unsigned*)act1, (unsigned*)act2, (unsigned*)act3,
                                   outConn, (float*)part);
    outfinal_kernel<<<BATCH, 320>>>((float*)part, preds_dst, outact_dst, (int*)cnt);
}